// round 8
// baseline (speedup 1.0000x reference)
#include <cuda_runtime.h>
#include <cuda_fp16.h>
#include <cstdint>

#define ALPHA 0.2f
#define NB 32
#define NN 128
#define FF 64
#define CC 128
#define BN (NB*NN)

static __device__ __forceinline__ float lrelu(float x) {
    return x >= 0.0f ? x : ALPHA * x;
}
static __device__ __forceinline__ uint32_t pack2(float lo, float hi) {
    __half2 h = __floats2half2_rn(lo, hi);
    return *(uint32_t*)&h;
}
static __device__ __forceinline__ void mma_f16(float c[4],
        uint32_t a0, uint32_t a1, uint32_t a2, uint32_t a3,
        uint32_t b0, uint32_t b1) {
    asm volatile(
        "mma.sync.aligned.m16n8k16.row.col.f32.f16.f16.f32 "
        "{%0,%1,%2,%3}, {%4,%5,%6,%7}, {%8,%9}, {%0,%1,%2,%3};\n"
        : "+f"(c[0]), "+f"(c[1]), "+f"(c[2]), "+f"(c[3])
        : "r"(a0), "r"(a1), "r"(a2), "r"(a3), "r"(b0), "r"(b1));
}

// Scratch
__device__ float g_Ac[BN * CC];
__device__ float g_An[BN * CC];
// fp16x2 B-fragment-ordered weights. Slot s = (ks*16+oct)*32+lane, ks in [0,8).
//   word s*2+0 = pack(W[k0  ][col], W[k0+1][col]),  k0 = ks*16+2*lc, col = oct*8+lr
//   word s*2+1 = pack(W[k0+8][col], W[k0+9][col])
// Read directly per-mma via coalesced 256B/warp LDG (L1-resident).
__device__ uint32_t g_W2h[CC * CC / 2];
__device__ uint32_t g_W3h[CC * CC / 2];

// ---------------------------------------------------------------------------
// Prep: layer-1 partials (all blocks) + weight permute (blocks 0..63).
// ---------------------------------------------------------------------------
__global__ void prep_k(const float* __restrict__ feats,
                       const float* __restrict__ W1,
                       const float* __restrict__ b1,
                       const float* __restrict__ W2,
                       const float* __restrict__ W3) {
    if (blockIdx.x < 64) {
        int t = blockIdx.x * 128 + threadIdx.x;   // 0..8191
        const float* W   = (t & 4096) ? W3 : W2;
        uint32_t*    dst = (t & 4096) ? g_W3h : g_W2h;
        int s    = t & 4095;
        int ks   = s >> 9;
        int oct  = (s >> 5) & 15;
        int lane = s & 31;
        int lrw = lane >> 2, lcw = lane & 3;
        int col = oct * 8 + lrw;
        int k0  = ks * 16 + 2 * lcw;
        dst[s * 2]     = pack2(W[k0 * CC + col],       W[(k0 + 1) * CC + col]);
        dst[s * 2 + 1] = pack2(W[(k0 + 8) * CC + col], W[(k0 + 9) * CC + col]);
    }
    int row = blockIdx.x;
    int c   = threadIdx.x;
    __shared__ float sf[FF];
    if (c < FF) sf[c] = feats[row * FF + c];
    __syncthreads();
    float accC = b1[c];
    float accN = 0.0f;
#pragma unroll
    for (int f = 0; f < FF; ++f) {
        float v = sf[f];
        accC = fmaf(v, W1[f * CC + c], accC);
        accN = fmaf(v, W1[(FF + f) * CC + c], accN);
    }
    g_Ac[row * CC + c] = accC;
    g_An[row * CC + c] = accN;
}

// ---------------------------------------------------------------------------
// Main: one block per (b,i). fp16 m16n8k16 mma. B fragments straight from
// global (L1-resident); smem only for activations.
// smem words: X2f 8192 | X1f 4096 | misc 644 = 50.5 KB -> 3 CTA/SM
// ---------------------------------------------------------------------------
__global__ __launch_bounds__(256, 3)
void edge_mlp_k(const int* __restrict__ mask,
                const float* __restrict__ b2,
                const float* __restrict__ b3,
                float* __restrict__ out) {
    extern __shared__ uint32_t smu[];
    uint32_t* sX2f = smu;                 // X2 A-fragment order, fp16x2
    uint32_t* sX1f = sX2f + 8192;         // X1 pass tile (64 rows)
    float* sCi   = (float*)(sX1f + 4096);
    float* sB2   = sCi + 128;
    float* sB3   = sB2 + 128;
    float* sMj   = sB3 + 128;
    float* sS    = sMj + 128;
    float* sMsum = sS + 128;

    const int tid  = threadIdx.x;
    const int wid  = tid >> 5;
    const int lane = tid & 31;
    const int lr   = lane >> 2;
    const int lc   = lane & 3;
    const int bi   = blockIdx.x;
    const int b    = bi >> 7;
    const int i    = bi & 127;
    const int bbase = b * NN;

    if (tid < 128) {
        sCi[tid] = g_Ac[bi * CC + tid];
        sB2[tid] = b2[tid];
        sB3[tid] = b3[tid];
        sS[tid]  = 0.0f;
        sMj[tid] = (mask[bbase + tid] != 0) ? 1.0f : 0.0f;
    }
    __syncthreads();
    if (tid == 0) {
        float s = 0.0f;
        for (int j = 0; j < NN; ++j) s += sMj[j];
        sMsum[0] = s;
    }

    // ================= GEMM1 over two 64-row passes (m=2,n=4) =============
    const int mg = wid & 1;   // 32-row half within pass
    const int ng = wid >> 1;  // 32-col group (4 octets)

    for (int p = 0; p < 2; ++p) {
        const int jb = p * 64;
        // --- build X1f (64 rows, fp16 A-fragment order); 1024 slots ---
#pragma unroll
        for (int u = 0; u < 4; ++u) {
            int s   = tid + u * 256;          // 0..1023
            int mt  = s >> 8;                 // 16-row mtile (0..3)
            int ks  = (s >> 5) & 7;
            int ln  = s & 31;
            int lrs = ln >> 2, lcs = ln & 3;
            int r0 = jb + mt * 16 + lrs, r1 = r0 + 8;
            int c0 = ks * 16 + 2 * lcs,  c1 = c0 + 8;
            float2 A0a = *(const float2*)&g_An[(bbase + r0) * CC + c0];
            float2 A0b = *(const float2*)&g_An[(bbase + r0) * CC + c1];
            float2 A1a = *(const float2*)&g_An[(bbase + r1) * CC + c0];
            float2 A1b = *(const float2*)&g_An[(bbase + r1) * CC + c1];
            float ci0 = sCi[c0], ci0b = sCi[c0 + 1];
            float ci1 = sCi[c1], ci1b = sCi[c1 + 1];
            uint4 v;
            v.x = pack2(lrelu(ci0 + A0a.x), lrelu(ci0b + A0a.y));
            v.y = pack2(lrelu(ci0 + A1a.x), lrelu(ci0b + A1a.y));
            v.z = pack2(lrelu(ci1 + A0b.x), lrelu(ci1b + A0b.y));
            v.w = pack2(lrelu(ci1 + A1b.x), lrelu(ci1b + A1b.y));
            *(uint4*)&sX1f[s * 4] = v;
        }
        __syncthreads();

        float acc[2][4][4];
#pragma unroll
        for (int mt = 0; mt < 2; ++mt)
#pragma unroll
            for (int of = 0; of < 4; ++of)
#pragma unroll
                for (int u = 0; u < 4; ++u) acc[mt][of][u] = 0.0f;

#pragma unroll
        for (int ks = 0; ks < 8; ++ks) {
            uint4 a0 = *(const uint4*)&sX1f[(((mg * 2 + 0) * 8 + ks) * 32 + lane) * 4];
            uint4 a1 = *(const uint4*)&sX1f[(((mg * 2 + 1) * 8 + ks) * 32 + lane) * 4];
#pragma unroll
            for (int of = 0; of < 4; ++of) {
                uint2 bb = __ldg((const uint2*)&g_W2h[((ks * 16 + ng * 4 + of) * 32 + lane) * 2]);
                mma_f16(acc[0][of], a0.x, a0.y, a0.z, a0.w, bb.x, bb.y);
                mma_f16(acc[1][of], a1.x, a1.y, a1.z, a1.w, bb.x, bb.y);
            }
        }

        // --- epilogue: bias+lrelu, pack fp16x2, write X2f A-frag order ---
#pragma unroll
        for (int mt = 0; mt < 2; ++mt) {
            int gmt = p * 4 + mg * 2 + mt;
#pragma unroll
            for (int of = 0; of < 4; ++of) {
                int oct = ng * 4 + of;
                int cb  = oct * 8 + 2 * lc;
                float e0 = lrelu(acc[mt][of][0] + sB2[cb]);
                float e1 = lrelu(acc[mt][of][1] + sB2[cb + 1]);
                float e2 = lrelu(acc[mt][of][2] + sB2[cb]);
                float e3 = lrelu(acc[mt][of][3] + sB2[cb + 1]);
                uint32_t base = ((gmt * 8 + (oct >> 1)) * 32 + lane) * 4 + (oct & 1) * 2;
                uint2 w;
                w.x = pack2(e0, e1);   // row lr
                w.y = pack2(e2, e3);   // row lr+8
                *(uint2*)&sX2f[base] = w;
            }
        }
        __syncthreads();
    }

    // ===== GEMM2: S[c] = sum_j m_j * lrelu(X2 @ W3 + b3)[j,c] =====
    // warp tile 32 rows x 64 cols, processed as two 32-col sweeps
    {
        const int mg2 = wid & 3;   // 32-row group
        const int ng2 = wid >> 2;  // 64-col group

#pragma unroll
        for (int ch = 0; ch < 2; ++ch) {
            float acc2[2][4][4];
#pragma unroll
            for (int mt = 0; mt < 2; ++mt)
#pragma unroll
                for (int of = 0; of < 4; ++of)
#pragma unroll
                    for (int u = 0; u < 4; ++u) acc2[mt][of][u] = 0.0f;

#pragma unroll
            for (int ks = 0; ks < 8; ++ks) {
                uint4 a0 = *(const uint4*)&sX2f[(((mg2 * 2 + 0) * 8 + ks) * 32 + lane) * 4];
                uint4 a1 = *(const uint4*)&sX2f[(((mg2 * 2 + 1) * 8 + ks) * 32 + lane) * 4];
#pragma unroll
                for (int of = 0; of < 4; ++of) {
                    int oct = ng2 * 8 + ch * 4 + of;
                    uint2 bb = __ldg((const uint2*)&g_W3h[((ks * 16 + oct) * 32 + lane) * 2]);
                    mma_f16(acc2[0][of], a0.x, a0.y, a0.z, a0.w, bb.x, bb.y);
                    mma_f16(acc2[1][of], a1.x, a1.y, a1.z, a1.w, bb.x, bb.y);
                }
            }

            // mask-weighted column sums
            float cs[4][2];
#pragma unroll
            for (int of = 0; of < 4; ++of) { cs[of][0] = 0.0f; cs[of][1] = 0.0f; }
#pragma unroll
            for (int mt = 0; mt < 2; ++mt) {
                int r0 = mg2 * 32 + mt * 16 + lr, r1 = r0 + 8;
                float m0 = sMj[r0], m1 = sMj[r1];
#pragma unroll
                for (int of = 0; of < 4; ++of) {
                    int cb = (ng2 * 8 + ch * 4 + of) * 8 + 2 * lc;
                    cs[of][0] += m0 * lrelu(acc2[mt][of][0] + sB3[cb])
                               + m1 * lrelu(acc2[mt][of][2] + sB3[cb]);
                    cs[of][1] += m0 * lrelu(acc2[mt][of][1] + sB3[cb + 1])
                               + m1 * lrelu(acc2[mt][of][3] + sB3[cb + 1]);
                }
            }
#pragma unroll
            for (int of = 0; of < 4; ++of) {
#pragma unroll
                for (int o = 0; o < 2; ++o) {
                    float v = cs[of][o];
                    v += __shfl_xor_sync(0xffffffffu, v, 4);
                    v += __shfl_xor_sync(0xffffffffu, v, 8);
                    v += __shfl_xor_sync(0xffffffffu, v, 16);
                    if (lr == 0)
                        atomicAdd(&sS[(ng2 * 8 + ch * 4 + of) * 8 + 2 * lc + o], v);
                }
            }
        }
    }
    __syncthreads();

    // ======= final masked mean + multiply_no_nan + lrelu =======
    if (tid < 128) {
        float miv = sMj[i];
        float num = miv * sS[tid];
        float den = miv * sMsum[0];
        float o;
        if (num == 0.0f) o = 0.0f;
        else             o = num / (den == 0.0f ? 1.0f : den);
        out[bi * CC + tid] = lrelu(o);
    }
}

// ---------------------------------------------------------------------------
extern "C" void kernel_launch(void* const* d_in, const int* in_sizes, int n_in,
                              void* d_out, int out_size) {
    const float* feats = (const float*)d_in[0];
    const int*   mask  = (const int*)d_in[1];
    const float* W1    = (const float*)d_in[2];
    const float* b1    = (const float*)d_in[3];
    const float* W2    = (const float*)d_in[4];
    const float* b2    = (const float*)d_in[5];
    const float* W3    = (const float*)d_in[6];
    const float* b3    = (const float*)d_in[7];
    float* out = (float*)d_out;

    prep_k<<<BN, 128>>>(feats, W1, b1, W2, W3);

    const size_t smem_bytes =
        (size_t)(8192 + 4096 + 5 * 128 + 4) * sizeof(uint32_t);
    cudaFuncSetAttribute(edge_mlp_k,
                         cudaFuncAttributeMaxDynamicSharedMemorySize,
                         (int)smem_bytes);
    edge_mlp_k<<<BN, 256, smem_bytes>>>(mask, b2, b3, out);
}

// round 12
// speedup vs baseline: 1.1959x; 1.1959x over previous
#include <cuda_runtime.h>
#include <cuda_fp16.h>
#include <cstdint>

#define ALPHA 0.2f
#define NB 32
#define NN 128
#define FF 64
#define CC 128
#define BN (NB*NN)

// smem layout (bytes)
#define SM_BF   0         // 32768: W2 fragments, later W3 (TMA-refilled)
#define SM_XF   32768     // 32768: X1 fragments, overwritten in-place by X2
#define SM_MISC 65536     // mbar0 @+0, mbar1 @+8, floats @+16
#define SMEM_TOTAL 68128

static __device__ __forceinline__ float lrelu(float x) { return x >= 0.0f ? x : ALPHA * x; }
static __device__ __forceinline__ uint32_t pack2(float lo, float hi) {
    __half2 h = __floats2half2_rn(lo, hi);
    return *(uint32_t*)&h;
}
static __device__ __forceinline__ uint32_t smem_u32(const void* p) {
    uint32_t a;
    asm("{ .reg .u64 t; cvta.to.shared.u64 t, %1; cvt.u32.u64 %0, t; }" : "=r"(a) : "l"(p));
    return a;
}
static __device__ __forceinline__ void mma_f16(float c[4],
        uint32_t a0, uint32_t a1, uint32_t a2, uint32_t a3,
        uint32_t b0, uint32_t b1) {
    asm volatile(
        "mma.sync.aligned.m16n8k16.row.col.f32.f16.f16.f32 "
        "{%0,%1,%2,%3}, {%4,%5,%6,%7}, {%8,%9}, {%0,%1,%2,%3};\n"
        : "+f"(c[0]), "+f"(c[1]), "+f"(c[2]), "+f"(c[3])
        : "r"(a0), "r"(a1), "r"(a2), "r"(a3), "r"(b0), "r"(b1));
}

#define MBAR_INIT(mbar, cnt) asm volatile("mbarrier.init.shared.b64 [%0], %1;" :: "r"(mbar), "r"((uint32_t)(cnt)) : "memory")
#define MBAR_INVAL(mbar)     asm volatile("mbarrier.inval.shared.b64 [%0];" :: "r"(mbar) : "memory")
#define MBAR_EXPECT_TX(mbar, bytes) \
    asm volatile("mbarrier.arrive.expect_tx.shared.b64 _, [%0], %1;" :: "r"(mbar), "r"((uint32_t)(bytes)) : "memory")
#define MBAR_WAIT(mbar, ph) do {                                              \
    asm volatile("{\n\t.reg .pred P1;\n\t"                                    \
        "WAIT_LOOP_%=:\n\t"                                                   \
        "mbarrier.try_wait.parity.acquire.cta.shared::cta.b64 P1, [%0], %1, 0x989680;\n\t" \
        "@P1 bra.uni WAIT_DONE_%=;\n\t"                                       \
        "bra.uni WAIT_LOOP_%=;\n\t"                                           \
        "WAIT_DONE_%=:\n\t}"                                                  \
        :: "r"(mbar), "r"((uint32_t)(ph)) : "memory");                        \
} while (0)
#define BULK_G2S(dst, src, bytes, mbar) \
    asm volatile("cp.async.bulk.shared::cluster.global.mbarrier::complete_tx::bytes [%0], [%1], %2, [%3];" \
        :: "r"(dst), "l"(src), "r"((uint32_t)(bytes)), "r"(mbar) : "memory")

// Scratch
__device__ float  g_Ac[BN * CC];
__device__ __half g_Anh[BN * CC];
// fp16x2 B-fragment-ordered weights. Slot s = (ks*16+oct)*32+lane, ks in [0,8).
//   word s*2+0 = pack(W[k0  ][col], W[k0+1][col]),  k0 = ks*16+2*lc, col = oct*8+lr
//   word s*2+1 = pack(W[k0+8][col], W[k0+9][col])
__device__ __align__(16) uint32_t g_W2h[CC * CC / 2];
__device__ __align__(16) uint32_t g_W3h[CC * CC / 2];

// ---------------------------------------------------------------------------
// Prep: layer-1 partials (g_Ac fp32, g_Anh fp16) + weight permute (blk 0..63).
// ---------------------------------------------------------------------------
__global__ void prep_k(const float* __restrict__ feats,
                       const float* __restrict__ W1,
                       const float* __restrict__ b1,
                       const float* __restrict__ W2,
                       const float* __restrict__ W3) {
    if (blockIdx.x < 64) {
        int t = blockIdx.x * 128 + threadIdx.x;   // 0..8191
        const float* W   = (t & 4096) ? W3 : W2;
        uint32_t*    dst = (t & 4096) ? g_W3h : g_W2h;
        int s    = t & 4095;                       // slot = (ks*16+oct)*32+lane
        int ks   = s >> 9;
        int oct  = (s >> 5) & 15;
        int lane = s & 31;
        int lrw = lane >> 2, lcw = lane & 3;
        int col = oct * 8 + lrw;
        int k0  = ks * 16 + 2 * lcw;
        dst[s * 2]     = pack2(W[k0 * CC + col],       W[(k0 + 1) * CC + col]);
        dst[s * 2 + 1] = pack2(W[(k0 + 8) * CC + col], W[(k0 + 9) * CC + col]);
    }
    int row = blockIdx.x;
    int c   = threadIdx.x;
    __shared__ float sf[FF];
    if (c < FF) sf[c] = feats[row * FF + c];
    __syncthreads();
    float accC = b1[c];
    float accN = 0.0f;
#pragma unroll
    for (int f = 0; f < FF; ++f) {
        float v = sf[f];
        accC = fmaf(v, W1[f * CC + c], accC);
        accN = fmaf(v, W1[(FF + f) * CC + c], accN);
    }
    g_Ac[row * CC + c]  = accC;
    g_Anh[row * CC + c] = __float2half(accN);
}

// ---------------------------------------------------------------------------
// Main: one block per (b,i). fp16 m16n8k16 mma; X1/X2 share one smem buffer
// (X2 overwrites X1 in-place, two 64-row sweeps); weights TMA'd into smem.
// smem 66.5KB -> 3 CTA/SM.
// ---------------------------------------------------------------------------
__global__ __launch_bounds__(256, 3)
void edge_mlp_k(const int* __restrict__ mask,
                const float* __restrict__ b2,
                const float* __restrict__ b3,
                float* __restrict__ out) {
    extern __shared__ char smem[];
    uint32_t* sBf = (uint32_t*)(smem + SM_BF);   // 8192 words, B fragments
    uint32_t* sXf = (uint32_t*)(smem + SM_XF);   // 8192 words, X fragments
    float* sCi   = (float*)(smem + SM_MISC + 16);
    float* sB2   = sCi + 128;
    float* sB3   = sB2 + 128;
    float* sMj   = sB3 + 128;
    float* sS    = sMj + 128;
    float* sMsum = sS + 128;

    const uint32_t smem_base = smem_u32(smem);
    const uint32_t mbar0 = smem_base + SM_MISC;
    const uint32_t mbar1 = smem_base + SM_MISC + 8;
    const uint32_t sbf_u32 = smem_base + SM_BF;

    const int tid  = threadIdx.x;
    const int wid  = tid >> 5;
    const int lane = tid & 31;
    const int lr   = lane >> 2;
    const int lc   = lane & 3;
    const int bi   = blockIdx.x;
    const int b    = bi >> 7;
    const int i    = bi & 127;
    const int bbase = b * NN;

    // --- stage misc + init mbarriers ---
    if (tid == 0) { MBAR_INIT(mbar0, 1); MBAR_INIT(mbar1, 1); }
    if (tid < 128) {
        sCi[tid] = g_Ac[bi * CC + tid];
        sB2[tid] = b2[tid];
        sB3[tid] = b3[tid];
        sS[tid]  = 0.0f;
        sMj[tid] = (mask[bbase + tid] != 0) ? 1.0f : 0.0f;
    }
    __syncthreads();

    // --- kick off W2 TMA (overlaps X1 build); tid0 also sums the mask ---
    if (tid == 0) {
        MBAR_EXPECT_TX(mbar0, 32768);
        BULK_G2S(sbf_u32, (const void*)g_W2h, 32768, mbar0);
        float s = 0.0f;
        for (int j = 0; j < NN; ++j) s += sMj[j];
        sMsum[0] = s;
    }

    // --- build full X1 (128 rows) in A-fragment order into sXf ---
#pragma unroll
    for (int u = 0; u < 8; ++u) {
        int s   = tid + u * 256;          // 0..2047
        int mt  = s >> 8;                 // 0..7
        int ks  = (s >> 5) & 7;
        int ln  = s & 31;
        int lrs = ln >> 2, lcs = ln & 3;
        int r0 = mt * 16 + lrs, r1 = r0 + 8;
        int c0 = ks * 16 + 2 * lcs, c1 = c0 + 8;
        float2 a00 = __half22float2(*(const __half2*)(g_Anh + (size_t)(bbase + r0) * CC + c0));
        float2 a01 = __half22float2(*(const __half2*)(g_Anh + (size_t)(bbase + r0) * CC + c1));
        float2 a10 = __half22float2(*(const __half2*)(g_Anh + (size_t)(bbase + r1) * CC + c0));
        float2 a11 = __half22float2(*(const __half2*)(g_Anh + (size_t)(bbase + r1) * CC + c1));
        float2 ci0 = *(const float2*)&sCi[c0];
        float2 ci1 = *(const float2*)&sCi[c1];
        uint4 v;
        v.x = pack2(lrelu(ci0.x + a00.x), lrelu(ci0.y + a00.y));
        v.y = pack2(lrelu(ci0.x + a10.x), lrelu(ci0.y + a10.y));
        v.z = pack2(lrelu(ci1.x + a01.x), lrelu(ci1.y + a01.y));
        v.w = pack2(lrelu(ci1.x + a11.x), lrelu(ci1.y + a11.y));
        *(uint4*)&sXf[s * 4] = v;
    }
    __syncthreads();
    MBAR_WAIT(mbar0, 0);   // W2 resident

    // ============ GEMM1: two 64-row sweeps, warp tile 32x32 ============
    const int mg = wid & 1;   // 32-row half within sweep
    const int ng = wid >> 1;  // 32-col group (4 octets)

#pragma unroll
    for (int sw = 0; sw < 2; ++sw) {
        const int mtb = sw * 4 + mg * 2;      // first of 2 mtiles
        float acc[2][4][4];
#pragma unroll
        for (int mt = 0; mt < 2; ++mt)
#pragma unroll
            for (int of = 0; of < 4; ++of)
#pragma unroll
                for (int u = 0; u < 4; ++u) acc[mt][of][u] = 0.0f;

#pragma unroll
        for (int ks = 0; ks < 8; ++ks) {
            uint4 a0 = *(const uint4*)&sXf[(((mtb + 0) * 8 + ks) * 32 + lane) * 4];
            uint4 a1 = *(const uint4*)&sXf[(((mtb + 1) * 8 + ks) * 32 + lane) * 4];
#pragma unroll
            for (int of = 0; of < 4; ++of) {
                uint2 bb = *(const uint2*)&sBf[((ks * 16 + ng * 4 + of) * 32 + lane) * 2];
                mma_f16(acc[0][of], a0.x, a0.y, a0.z, a0.w, bb.x, bb.y);
                mma_f16(acc[1][of], a1.x, a1.y, a1.z, a1.w, bb.x, bb.y);
            }
        }
        __syncthreads();   // all warps done reading this sweep's X1 region

        if (sw == 1 && tid == 0) {            // refill sBf with W3 under epi
            MBAR_EXPECT_TX(mbar1, 32768);
            BULK_G2S(sbf_u32, (const void*)g_W3h, 32768, mbar1);
        }

        // epilogue: bias+lrelu, pack fp16x2, write X2 over X1 (same rows)
#pragma unroll
        for (int mt = 0; mt < 2; ++mt) {
            int gmt = mtb + mt;
#pragma unroll
            for (int of = 0; of < 4; ++of) {
                int oct = ng * 4 + of;
                int cb  = oct * 8 + 2 * lc;
                float e0 = lrelu(acc[mt][of][0] + sB2[cb]);
                float e1 = lrelu(acc[mt][of][1] + sB2[cb + 1]);
                float e2 = lrelu(acc[mt][of][2] + sB2[cb]);
                float e3 = lrelu(acc[mt][of][3] + sB2[cb + 1]);
                uint32_t base = ((gmt * 8 + (oct >> 1)) * 32 + lane) * 4 + (oct & 1) * 2;
                uint2 w;
                w.x = pack2(e0, e1);   // row lr
                w.y = pack2(e2, e3);   // row lr+8
                *(uint2*)&sXf[base] = w;
            }
        }
        __syncthreads();
    }
    MBAR_WAIT(mbar1, 0);   // W3 resident

    // ===== GEMM2: S[c] = sum_j m_j * lrelu(X2 @ W3 + b3)[j,c] =====
    {
        float cs[4][2];
#pragma unroll
        for (int of = 0; of < 4; ++of) { cs[of][0] = 0.0f; cs[of][1] = 0.0f; }

#pragma unroll
        for (int sw = 0; sw < 2; ++sw) {
            const int mtb = sw * 4 + mg * 2;
            float acc2[2][4][4];
#pragma unroll
            for (int mt = 0; mt < 2; ++mt)
#pragma unroll
                for (int of = 0; of < 4; ++of)
#pragma unroll
                    for (int u = 0; u < 4; ++u) acc2[mt][of][u] = 0.0f;

#pragma unroll
            for (int ks = 0; ks < 8; ++ks) {
                uint4 a0 = *(const uint4*)&sXf[(((mtb + 0) * 8 + ks) * 32 + lane) * 4];
                uint4 a1 = *(const uint4*)&sXf[(((mtb + 1) * 8 + ks) * 32 + lane) * 4];
#pragma unroll
                for (int of = 0; of < 4; ++of) {
                    uint2 bb = *(const uint2*)&sBf[((ks * 16 + ng * 4 + of) * 32 + lane) * 2];
                    mma_f16(acc2[0][of], a0.x, a0.y, a0.z, a0.w, bb.x, bb.y);
                    mma_f16(acc2[1][of], a1.x, a1.y, a1.z, a1.w, bb.x, bb.y);
                }
            }
            // mask-weighted column sums (accumulate across sweeps)
#pragma unroll
            for (int mt = 0; mt < 2; ++mt) {
                int r0 = (mtb + mt) * 16 + lr, r1 = r0 + 8;
                float m0 = sMj[r0], m1 = sMj[r1];
#pragma unroll
                for (int of = 0; of < 4; ++of) {
                    int cb = (ng * 4 + of) * 8 + 2 * lc;
                    cs[of][0] += m0 * lrelu(acc2[mt][of][0] + sB3[cb])
                               + m1 * lrelu(acc2[mt][of][2] + sB3[cb]);
                    cs[of][1] += m0 * lrelu(acc2[mt][of][1] + sB3[cb + 1])
                               + m1 * lrelu(acc2[mt][of][3] + sB3[cb + 1]);
                }
            }
        }
#pragma unroll
        for (int of = 0; of < 4; ++of) {
#pragma unroll
            for (int o = 0; o < 2; ++o) {
                float v = cs[of][o];
                v += __shfl_xor_sync(0xffffffffu, v, 4);
                v += __shfl_xor_sync(0xffffffffu, v, 8);
                v += __shfl_xor_sync(0xffffffffu, v, 16);
                if (lr == 0)
                    atomicAdd(&sS[(ng * 4 + of) * 8 + 2 * lc + o], v);
            }
        }
    }
    __syncthreads();

    // ======= final masked mean + multiply_no_nan + lrelu =======
    if (tid < 128) {
        float miv = sMj[i];
        float num = miv * sS[tid];
        float den = miv * sMsum[0];
        float o;
        if (num == 0.0f) o = 0.0f;
        else             o = num / (den == 0.0f ? 1.0f : den);
        out[bi * CC + tid] = lrelu(o);
    }
    __syncthreads();
    if (tid == 0) { MBAR_INVAL(mbar0); MBAR_INVAL(mbar1); }
}

// ---------------------------------------------------------------------------
extern "C" void kernel_launch(void* const* d_in, const int* in_sizes, int n_in,
                              void* d_out, int out_size) {
    const float* feats = (const float*)d_in[0];
    const int*   mask  = (const int*)d_in[1];
    const float* W1    = (const float*)d_in[2];
    const float* b1    = (const float*)d_in[3];
    const float* W2    = (const float*)d_in[4];
    const float* b2    = (const float*)d_in[5];
    const float* W3    = (const float*)d_in[6];
    const float* b3    = (const float*)d_in[7];
    float* out = (float*)d_out;

    prep_k<<<BN, 128>>>(feats, W1, b1, W2, W3);

    cudaFuncSetAttribute(edge_mlp_k,
                         cudaFuncAttributeMaxDynamicSharedMemorySize,
                         SMEM_TOTAL);
    edge_mlp_k<<<BN, 256, SMEM_TOTAL>>>(mask, b2, b3, out);
}

// round 15
// speedup vs baseline: 1.4004x; 1.1711x over previous
#include <cuda_runtime.h>
#include <cuda_fp16.h>
#include <cstdint>

#define ALPHA 0.2f
#define NB 32
#define NN 128
#define FF 64
#define CC 128
#define BN (NB*NN)

// smem layout (bytes)
#define SM_BF   0         // 32768: W2 fragments, later W3 (sync-refilled)
#define SM_XF0  32768     // 32768: tile0 X1/X2 fragments (in-place)
#define SM_XF1  65536     // 32768: tile1
#define SM_MISC 98304     // floats
#define SMEM_TOTAL 102048

static __device__ __forceinline__ float lrelu(float x) { return x >= 0.0f ? x : ALPHA * x; }
static __device__ __forceinline__ uint32_t pack2(float lo, float hi) {
    __half2 h = __floats2half2_rn(lo, hi);
    return *(uint32_t*)&h;
}
static __device__ __forceinline__ void mma_f16(float c[4],
        uint32_t a0, uint32_t a1, uint32_t a2, uint32_t a3,
        uint32_t b0, uint32_t b1) {
    asm volatile(
        "mma.sync.aligned.m16n8k16.row.col.f32.f16.f16.f32 "
        "{%0,%1,%2,%3}, {%4,%5,%6,%7}, {%8,%9}, {%0,%1,%2,%3};\n"
        : "+f"(c[0]), "+f"(c[1]), "+f"(c[2]), "+f"(c[3])
        : "r"(a0), "r"(a1), "r"(a2), "r"(a3), "r"(b0), "r"(b1));
}

// Scratch
__device__ float  g_Ac[BN * CC];
__device__ __half g_Anh[BN * CC];
// fp16x2 B-fragment-ordered weights. Slot s = (ks*16+oct)*32+lane, ks in [0,8).
__device__ __align__(16) uint32_t g_W2h[CC * CC / 2];
__device__ __align__(16) uint32_t g_W3h[CC * CC / 2];

// ---------------------------------------------------------------------------
// Prep: layer-1 partials (g_Ac fp32, g_Anh fp16) + weight permute (blk 0..63).
// ---------------------------------------------------------------------------
__global__ void prep_k(const float* __restrict__ feats,
                       const float* __restrict__ W1,
                       const float* __restrict__ b1,
                       const float* __restrict__ W2,
                       const float* __restrict__ W3) {
    if (blockIdx.x < 64) {
        int t = blockIdx.x * 128 + threadIdx.x;   // 0..8191
        const float* W   = (t & 4096) ? W3 : W2;
        uint32_t*    dst = (t & 4096) ? g_W3h : g_W2h;
        int s    = t & 4095;
        int ks   = s >> 9;
        int oct  = (s >> 5) & 15;
        int lane = s & 31;
        int lrw = lane >> 2, lcw = lane & 3;
        int col = oct * 8 + lrw;
        int k0  = ks * 16 + 2 * lcw;
        dst[s * 2]     = pack2(W[k0 * CC + col],       W[(k0 + 1) * CC + col]);
        dst[s * 2 + 1] = pack2(W[(k0 + 8) * CC + col], W[(k0 + 9) * CC + col]);
    }
    int row = blockIdx.x;
    int c   = threadIdx.x;
    __shared__ float sf[FF];
    if (c < FF) sf[c] = feats[row * FF + c];
    __syncthreads();
    float accC = b1[c];
    float accN = 0.0f;
#pragma unroll
    for (int f = 0; f < FF; ++f) {
        float v = sf[f];
        accC = fmaf(v, W1[f * CC + c], accC);
        accN = fmaf(v, W1[(FF + f) * CC + c], accN);
    }
    g_Ac[row * CC + c]  = accC;
    g_Anh[row * CC + c] = __float2half(accN);
}

// ---------------------------------------------------------------------------
// Main: one block per PAIR of (b,i) tiles (i = 2s, 2s+1; same batch b).
// B fragments loaded once per ks/octet and reused for both tiles.
// X2 stored in conflict-free pair-plane layout:
//   word = ((mt*8+ks)*2 + pr)*64 + lane*2 + w   (pr: (a0,a1) vs (a2,a3))
// Weight staging: plain synchronous LDG->STS (no TMA/mbarrier).
// ---------------------------------------------------------------------------
__global__ __launch_bounds__(256, 2)
void edge_mlp_k(const int* __restrict__ mask,
                const float* __restrict__ b2,
                const float* __restrict__ b3,
                float* __restrict__ out) {
    extern __shared__ char smem[];
    uint32_t* sBf  = (uint32_t*)(smem + SM_BF);
    uint32_t* sXf0 = (uint32_t*)(smem + SM_XF0);
    uint32_t* sXf1 = (uint32_t*)(smem + SM_XF1);
    float* sCi0  = (float*)(smem + SM_MISC);
    float* sCi1  = sCi0 + 128;
    float* sB2   = sCi1 + 128;
    float* sB3   = sB2 + 128;
    float* sMj   = sB3 + 128;
    float* sS0   = sMj + 128;
    float* sS1   = sS0 + 128;
    float* sMsum = sS1 + 128;

    const int tid  = threadIdx.x;
    const int wid  = tid >> 5;
    const int lane = tid & 31;
    const int lr   = lane >> 2;
    const int lc   = lane & 3;
    const int bi0  = blockIdx.x * 2;
    const int bi1  = bi0 + 1;
    const int b    = bi0 >> 7;
    const int i0   = bi0 & 127;
    const int i1   = i0 + 1;
    const int bbase = b * NN;

    // --- stage W2 fragments (coalesced uint4) + misc ---
    {
        const uint4* src = (const uint4*)g_W2h;
        uint4* dst = (uint4*)sBf;
#pragma unroll
        for (int u = 0; u < 8; ++u) dst[tid + u * 256] = src[tid + u * 256];
    }
    if (tid < 128) {
        sCi0[tid] = g_Ac[bi0 * CC + tid];
        sCi1[tid] = g_Ac[bi1 * CC + tid];
        sB2[tid]  = b2[tid];
        sB3[tid]  = b3[tid];
        sS0[tid]  = 0.0f;
        sS1[tid]  = 0.0f;
        sMj[tid]  = (mask[bbase + tid] != 0) ? 1.0f : 0.0f;
    }
    __syncthreads();
    if (tid == 0) {
        float s = 0.0f;
        for (int j = 0; j < NN; ++j) s += sMj[j];
        sMsum[0] = s;
    }

    // --- build X1 for BOTH tiles (An loaded once) in A-fragment order ---
#pragma unroll
    for (int u = 0; u < 8; ++u) {
        int s   = tid + u * 256;          // 0..2047
        int mt  = s >> 8;
        int ks  = (s >> 5) & 7;
        int ln  = s & 31;
        int lrs = ln >> 2, lcs = ln & 3;
        int r0 = mt * 16 + lrs, r1 = r0 + 8;
        int c0 = ks * 16 + 2 * lcs, c1 = c0 + 8;
        float2 a00 = __half22float2(*(const __half2*)(g_Anh + (size_t)(bbase + r0) * CC + c0));
        float2 a01 = __half22float2(*(const __half2*)(g_Anh + (size_t)(bbase + r0) * CC + c1));
        float2 a10 = __half22float2(*(const __half2*)(g_Anh + (size_t)(bbase + r1) * CC + c0));
        float2 a11 = __half22float2(*(const __half2*)(g_Anh + (size_t)(bbase + r1) * CC + c1));
        float2 p0 = *(const float2*)&sCi0[c0];
        float2 p1 = *(const float2*)&sCi0[c1];
        float2 q0 = *(const float2*)&sCi1[c0];
        float2 q1 = *(const float2*)&sCi1[c1];
        uint4 v0, v1;
        v0.x = pack2(lrelu(p0.x + a00.x), lrelu(p0.y + a00.y));
        v0.y = pack2(lrelu(p0.x + a10.x), lrelu(p0.y + a10.y));
        v0.z = pack2(lrelu(p1.x + a01.x), lrelu(p1.y + a01.y));
        v0.w = pack2(lrelu(p1.x + a11.x), lrelu(p1.y + a11.y));
        v1.x = pack2(lrelu(q0.x + a00.x), lrelu(q0.y + a00.y));
        v1.y = pack2(lrelu(q0.x + a10.x), lrelu(q0.y + a10.y));
        v1.z = pack2(lrelu(q1.x + a01.x), lrelu(q1.y + a01.y));
        v1.w = pack2(lrelu(q1.x + a11.x), lrelu(q1.y + a11.y));
        *(uint4*)&sXf0[s * 4] = v0;
        *(uint4*)&sXf1[s * 4] = v1;
    }
    __syncthreads();

    const int mg = wid & 1;   // 32-row half within sweep
    const int ng = wid >> 1;  // 32-col group (4 octets)

    // ============ GEMM1: two 64-row sweeps, both tiles, B reused ============
#pragma unroll
    for (int sw = 0; sw < 2; ++sw) {
        const int mtb = sw * 4 + mg * 2;
        float acc[2][2][4][4];   // [tile][mt][of][4]
#pragma unroll
        for (int t = 0; t < 2; ++t)
#pragma unroll
            for (int mt = 0; mt < 2; ++mt)
#pragma unroll
                for (int of = 0; of < 4; ++of)
#pragma unroll
                    for (int u = 0; u < 4; ++u) acc[t][mt][of][u] = 0.0f;

#pragma unroll
        for (int ks = 0; ks < 8; ++ks) {
            uint4 a00 = *(const uint4*)&sXf0[(((mtb + 0) * 8 + ks) * 32 + lane) * 4];
            uint4 a01 = *(const uint4*)&sXf0[(((mtb + 1) * 8 + ks) * 32 + lane) * 4];
            uint4 a10 = *(const uint4*)&sXf1[(((mtb + 0) * 8 + ks) * 32 + lane) * 4];
            uint4 a11 = *(const uint4*)&sXf1[(((mtb + 1) * 8 + ks) * 32 + lane) * 4];
#pragma unroll
            for (int of = 0; of < 4; ++of) {
                uint2 bb = *(const uint2*)&sBf[((ks * 16 + ng * 4 + of) * 32 + lane) * 2];
                mma_f16(acc[0][0][of], a00.x, a00.y, a00.z, a00.w, bb.x, bb.y);
                mma_f16(acc[0][1][of], a01.x, a01.y, a01.z, a01.w, bb.x, bb.y);
                mma_f16(acc[1][0][of], a10.x, a10.y, a10.z, a10.w, bb.x, bb.y);
                mma_f16(acc[1][1][of], a11.x, a11.y, a11.z, a11.w, bb.x, bb.y);
            }
        }
        __syncthreads();   // all warps done reading this sweep's X1 region

        // epilogue: bias+lrelu, pack fp16x2, write X2 (pair-plane layout)
#pragma unroll
        for (int t = 0; t < 2; ++t) {
            uint32_t* sXf = t ? sXf1 : sXf0;
#pragma unroll
            for (int mt = 0; mt < 2; ++mt) {
                int gmt = mtb + mt;
#pragma unroll
                for (int of = 0; of < 4; ++of) {
                    int oct = ng * 4 + of;
                    int cb  = oct * 8 + 2 * lc;
                    float e0 = lrelu(acc[t][mt][of][0] + sB2[cb]);
                    float e1 = lrelu(acc[t][mt][of][1] + sB2[cb + 1]);
                    float e2 = lrelu(acc[t][mt][of][2] + sB2[cb]);
                    float e3 = lrelu(acc[t][mt][of][3] + sB2[cb + 1]);
                    uint32_t base = (((gmt * 8 + (oct >> 1)) * 2 + (oct & 1)) * 64 + lane * 2);
                    uint2 w;
                    w.x = pack2(e0, e1);   // (a0,a1) word pair
                    w.y = pack2(e2, e3);   // (a2,a3) word pair
                    *(uint2*)&sXf[base] = w;
                }
            }
        }
        __syncthreads();
    }

    // --- swap to W3 fragments (synchronous) ---
    {
        const uint4* src = (const uint4*)g_W3h;
        uint4* dst = (uint4*)sBf;
#pragma unroll
        for (int u = 0; u < 8; ++u) dst[tid + u * 256] = src[tid + u * 256];
    }
    __syncthreads();

    // ===== GEMM2: S_t[c] = sum_j m_j * lrelu(X2_t @ W3 + b3)[j,c] =====
    {
        float cs[2][4][2];
#pragma unroll
        for (int t = 0; t < 2; ++t)
#pragma unroll
            for (int of = 0; of < 4; ++of) { cs[t][of][0] = 0.0f; cs[t][of][1] = 0.0f; }

#pragma unroll
        for (int sw = 0; sw < 2; ++sw) {
            const int mtb = sw * 4 + mg * 2;
            float acc[2][2][4][4];
#pragma unroll
            for (int t = 0; t < 2; ++t)
#pragma unroll
                for (int mt = 0; mt < 2; ++mt)
#pragma unroll
                    for (int of = 0; of < 4; ++of)
#pragma unroll
                        for (int u = 0; u < 4; ++u) acc[t][mt][of][u] = 0.0f;

#pragma unroll
            for (int ks = 0; ks < 8; ++ks) {
                uint32_t base0 = ((mtb + 0) * 8 + ks) * 128 + lane * 2;
                uint32_t base1 = ((mtb + 1) * 8 + ks) * 128 + lane * 2;
                uint2 p00 = *(const uint2*)&sXf0[base0];
                uint2 p01 = *(const uint2*)&sXf0[base0 + 64];
                uint2 p10 = *(const uint2*)&sXf0[base1];
                uint2 p11 = *(const uint2*)&sXf0[base1 + 64];
                uint2 q00 = *(const uint2*)&sXf1[base0];
                uint2 q01 = *(const uint2*)&sXf1[base0 + 64];
                uint2 q10 = *(const uint2*)&sXf1[base1];
                uint2 q11 = *(const uint2*)&sXf1[base1 + 64];
#pragma unroll
                for (int of = 0; of < 4; ++of) {
                    uint2 bb = *(const uint2*)&sBf[((ks * 16 + ng * 4 + of) * 32 + lane) * 2];
                    mma_f16(acc[0][0][of], p00.x, p00.y, p01.x, p01.y, bb.x, bb.y);
                    mma_f16(acc[0][1][of], p10.x, p10.y, p11.x, p11.y, bb.x, bb.y);
                    mma_f16(acc[1][0][of], q00.x, q00.y, q01.x, q01.y, bb.x, bb.y);
                    mma_f16(acc[1][1][of], q10.x, q10.y, q11.x, q11.y, bb.x, bb.y);
                }
            }
            // mask-weighted column sums (accumulate across sweeps)
#pragma unroll
            for (int t = 0; t < 2; ++t)
#pragma unroll
                for (int mt = 0; mt < 2; ++mt) {
                    int r0 = (mtb + mt) * 16 + lr, r1 = r0 + 8;
                    float m0 = sMj[r0], m1 = sMj[r1];
#pragma unroll
                    for (int of = 0; of < 4; ++of) {
                        int cb = (ng * 4 + of) * 8 + 2 * lc;
                        cs[t][of][0] += m0 * lrelu(acc[t][mt][of][0] + sB3[cb])
                                      + m1 * lrelu(acc[t][mt][of][2] + sB3[cb]);
                        cs[t][of][1] += m0 * lrelu(acc[t][mt][of][1] + sB3[cb + 1])
                                      + m1 * lrelu(acc[t][mt][of][3] + sB3[cb + 1]);
                    }
                }
        }
#pragma unroll
        for (int t = 0; t < 2; ++t) {
            float* sS = t ? sS1 : sS0;
#pragma unroll
            for (int of = 0; of < 4; ++of) {
#pragma unroll
                for (int o = 0; o < 2; ++o) {
                    float v = cs[t][of][o];
                    v += __shfl_xor_sync(0xffffffffu, v, 4);
                    v += __shfl_xor_sync(0xffffffffu, v, 8);
                    v += __shfl_xor_sync(0xffffffffu, v, 16);
                    if (lr == 0)
                        atomicAdd(&sS[(ng * 4 + of) * 8 + 2 * lc + o], v);
                }
            }
        }
    }
    __syncthreads();

    // ======= final masked mean + multiply_no_nan + lrelu (both tiles) =======
    {
        int c = tid & 127;
        int t = tid >> 7;
        float miv = sMj[t ? i1 : i0];
        float num = miv * (t ? sS1[c] : sS0[c]);
        float den = miv * sMsum[0];
        float o;
        if (num == 0.0f) o = 0.0f;
        else             o = num / (den == 0.0f ? 1.0f : den);
        out[(t ? bi1 : bi0) * CC + c] = lrelu(o);
    }
}

// ---------------------------------------------------------------------------
extern "C" void kernel_launch(void* const* d_in, const int* in_sizes, int n_in,
                              void* d_out, int out_size) {
    const float* feats = (const float*)d_in[0];
    const int*   mask  = (const int*)d_in[1];
    const float* W1    = (const float*)d_in[2];
    const float* b1    = (const float*)d_in[3];
    const float* W2    = (const float*)d_in[4];
    const float* b2    = (const float*)d_in[5];
    const float* W3    = (const float*)d_in[6];
    const float* b3    = (const float*)d_in[7];
    float* out = (float*)d_out;

    prep_k<<<BN, 128>>>(feats, W1, b1, W2, W3);

    cudaFuncSetAttribute(edge_mlp_k,
                         cudaFuncAttributeMaxDynamicSharedMemorySize,
                         SMEM_TOTAL);
    edge_mlp_k<<<BN / 2, 256, SMEM_TOTAL>>>(mask, b2, b3, out);
}

// round 17
// speedup vs baseline: 1.5129x; 1.0803x over previous
#include <cuda_runtime.h>
#include <cuda_fp16.h>
#include <cstdint>

#define ALPHA 0.2f
#define NB 32
#define NN 128
#define FF 64
#define CC 128
#define BN (NB*NN)

// smem layout (bytes)
#define SM_BF   0         // 32768: W2 fragments, later W3 (cp.async-refilled)
#define SM_XF0  32768     // 32768: tile0 X1/X2 fragments (in-place)
#define SM_XF1  65536     // 32768: tile1
#define SM_MISC 98304     // floats
#define SMEM_TOTAL 102048

static __device__ __forceinline__ float lrelu(float x) { return x >= 0.0f ? x : ALPHA * x; }
static __device__ __forceinline__ uint32_t pack2(float lo, float hi) {
    __half2 h = __floats2half2_rn(lo, hi);
    return *(uint32_t*)&h;
}
static __device__ __forceinline__ uint32_t smem_u32(const void* p) {
    uint32_t a;
    asm("{ .reg .u64 t; cvta.to.shared.u64 t, %1; cvt.u32.u64 %0, t; }" : "=r"(a) : "l"(p));
    return a;
}
static __device__ __forceinline__ void mma_f16(float c[4],
        uint32_t a0, uint32_t a1, uint32_t a2, uint32_t a3,
        uint32_t b0, uint32_t b1) {
    asm volatile(
        "mma.sync.aligned.m16n8k16.row.col.f32.f16.f16.f32 "
        "{%0,%1,%2,%3}, {%4,%5,%6,%7}, {%8,%9}, {%0,%1,%2,%3};\n"
        : "+f"(c[0]), "+f"(c[1]), "+f"(c[2]), "+f"(c[3])
        : "r"(a0), "r"(a1), "r"(a2), "r"(a3), "r"(b0), "r"(b1));
}

#define CP_ASYNC16(dst, src) \
    asm volatile("cp.async.cg.shared.global [%0], [%1], 16;" :: "r"(dst), "l"(src) : "memory")
#define CP_COMMIT() asm volatile("cp.async.commit_group;" ::: "memory")
#define CP_WAIT0()  asm volatile("cp.async.wait_group 0;" ::: "memory")

// Scratch
__device__ float g_Ac[BN * CC];
// An in A-fragment order, per batch: word ((b*2048 + s)*4 + w),
//   s=(mt*8+ks)*32+ln, w: 0=(r0,c0 pair) 1=(r1,c0 pair) 2=(r0,c1 pair) 3=(r1,c1 pair)
__device__ __align__(16) uint32_t g_Anf[NB * 8192];
// fp16x2 B-fragment-ordered weights. Slot s = (ks*16+oct)*32+lane, ks in [0,8).
__device__ __align__(16) uint32_t g_W2h[CC * CC / 2];
__device__ __align__(16) uint32_t g_W3h[CC * CC / 2];

// ---------------------------------------------------------------------------
// Prep: layer-1 partials (g_Ac fp32, g_Anf fp16-fragment) + weight permute.
// ---------------------------------------------------------------------------
__global__ void prep_k(const float* __restrict__ feats,
                       const float* __restrict__ W1,
                       const float* __restrict__ b1,
                       const float* __restrict__ W2,
                       const float* __restrict__ W3) {
    if (blockIdx.x < 64) {
        int t = blockIdx.x * 128 + threadIdx.x;   // 0..8191
        const float* W   = (t & 4096) ? W3 : W2;
        uint32_t*    dst = (t & 4096) ? g_W3h : g_W2h;
        int s    = t & 4095;
        int ks   = s >> 9;
        int oct  = (s >> 5) & 15;
        int lane = s & 31;
        int lrw = lane >> 2, lcw = lane & 3;
        int col = oct * 8 + lrw;
        int k0  = ks * 16 + 2 * lcw;
        dst[s * 2]     = pack2(W[k0 * CC + col],       W[(k0 + 1) * CC + col]);
        dst[s * 2 + 1] = pack2(W[(k0 + 8) * CC + col], W[(k0 + 9) * CC + col]);
    }
    int row = blockIdx.x;
    int c   = threadIdx.x;
    __shared__ float sf[FF];
    if (c < FF) sf[c] = feats[row * FF + c];
    __syncthreads();
    float accC = b1[c];
    float accN = 0.0f;
#pragma unroll
    for (int f = 0; f < FF; ++f) {
        float v = sf[f];
        accC = fmaf(v, W1[f * CC + c], accC);
        accN = fmaf(v, W1[(FF + f) * CC + c], accN);
    }
    g_Ac[row * CC + c] = accC;
    // write An pair into fragment layout
    float hiN = __shfl_down_sync(0xffffffffu, accN, 1);
    if ((c & 1) == 0) {
        int bb  = row >> 7;
        int rr  = row & 127;
        int mt  = rr >> 4;
        int hi  = (rr >> 3) & 1;
        int lrs = rr & 7;
        int ks  = c >> 4;
        int rem = c & 15;
        int lcs = (rem >> 1) & 3;
        int ln  = lrs * 4 + lcs;
        int s   = (mt * 8 + ks) * 32 + ln;
        int w   = ((rem >= 8) ? 2 : 0) + hi;
        g_Anf[((bb << 11) + s) * 4 + w] = pack2(accN, hiN);
    }
}

// ---------------------------------------------------------------------------
// Main: one block per PAIR of (b,i) tiles. B fragments reused across tiles;
// X2 over X1 in-place (pair-plane layout); cp.async weight staging overlapped
// with X1 build (W2) and sweep-1 epilogue (W3).
// ---------------------------------------------------------------------------
__global__ __launch_bounds__(256, 2)
void edge_mlp_k(const int* __restrict__ mask,
                const float* __restrict__ b2,
                const float* __restrict__ b3,
                float* __restrict__ out) {
    extern __shared__ char smem[];
    uint32_t* sBf  = (uint32_t*)(smem + SM_BF);
    uint32_t* sXf0 = (uint32_t*)(smem + SM_XF0);
    uint32_t* sXf1 = (uint32_t*)(smem + SM_XF1);
    float* sCi0  = (float*)(smem + SM_MISC);
    float* sCi1  = sCi0 + 128;
    float* sB2   = sCi1 + 128;
    float* sB3   = sB2 + 128;
    float* sMj   = sB3 + 128;
    float* sS0   = sMj + 128;
    float* sS1   = sS0 + 128;
    float* sMsum = sS1 + 128;

    const int tid  = threadIdx.x;
    const int wid  = tid >> 5;
    const int lane = tid & 31;
    const int lr   = lane >> 2;
    const int lc   = lane & 3;
    const int bi0  = blockIdx.x * 2;
    const int bi1  = bi0 + 1;
    const int b    = bi0 >> 7;
    const int i0   = bi0 & 127;
    const int i1   = i0 + 1;
    const int bbase = b * NN;
    const uint32_t bf_u32 = smem_u32(smem + SM_BF);

    // --- kick off W2 cp.async (overlaps misc staging + X1 build) ---
#pragma unroll
    for (int u = 0; u < 8; ++u) {
        int idx = tid + u * 256;
        CP_ASYNC16(bf_u32 + idx * 16, (const char*)g_W2h + idx * 16);
    }
    CP_COMMIT();

    if (tid < 128) {
        sCi0[tid] = g_Ac[bi0 * CC + tid];
        sCi1[tid] = g_Ac[bi1 * CC + tid];
        sB2[tid]  = b2[tid];
        sB3[tid]  = b3[tid];
        sS0[tid]  = 0.0f;
        sS1[tid]  = 0.0f;
        sMj[tid]  = (mask[bbase + tid] != 0) ? 1.0f : 0.0f;
    }
    __syncthreads();
    if (tid == 0) {
        float s = 0.0f;
        for (int j = 0; j < NN; ++j) s += sMj[j];
        sMsum[0] = s;
    }

    // --- build X1 for BOTH tiles: coalesced uint4 An-fragment loads ---
    {
        const uint32_t* anf = g_Anf + ((size_t)b << 13);
#pragma unroll
        for (int u = 0; u < 8; ++u) {
            int s   = tid + u * 256;          // 0..2047
            int ks  = (s >> 5) & 7;
            int lcs = s & 3;
            int c0 = ks * 16 + 2 * lcs, c1 = c0 + 8;
            uint4 an = *(const uint4*)&anf[s * 4];
            float2 a00 = __half22float2(*(__half2*)&an.x);
            float2 a10 = __half22float2(*(__half2*)&an.y);
            float2 a01 = __half22float2(*(__half2*)&an.z);
            float2 a11 = __half22float2(*(__half2*)&an.w);
            float2 p0 = *(const float2*)&sCi0[c0];
            float2 p1 = *(const float2*)&sCi0[c1];
            float2 q0 = *(const float2*)&sCi1[c0];
            float2 q1 = *(const float2*)&sCi1[c1];
            uint4 v0, v1;
            v0.x = pack2(lrelu(p0.x + a00.x), lrelu(p0.y + a00.y));
            v0.y = pack2(lrelu(p0.x + a10.x), lrelu(p0.y + a10.y));
            v0.z = pack2(lrelu(p1.x + a01.x), lrelu(p1.y + a01.y));
            v0.w = pack2(lrelu(p1.x + a11.x), lrelu(p1.y + a11.y));
            v1.x = pack2(lrelu(q0.x + a00.x), lrelu(q0.y + a00.y));
            v1.y = pack2(lrelu(q0.x + a10.x), lrelu(q0.y + a10.y));
            v1.z = pack2(lrelu(q1.x + a01.x), lrelu(q1.y + a01.y));
            v1.w = pack2(lrelu(q1.x + a11.x), lrelu(q1.y + a11.y));
            *(uint4*)&sXf0[s * 4] = v0;
            *(uint4*)&sXf1[s * 4] = v1;
        }
    }
    CP_WAIT0();        // W2 resident (own group), then barrier covers all
    __syncthreads();

    const int mg = wid & 1;   // 32-row half within sweep
    const int ng = wid >> 1;  // 32-col group (4 octets)

    // ============ GEMM1: two 64-row sweeps, both tiles, B reused ============
#pragma unroll
    for (int sw = 0; sw < 2; ++sw) {
        const int mtb = sw * 4 + mg * 2;
        float acc[2][2][4][4];   // [tile][mt][of][4]
#pragma unroll
        for (int t = 0; t < 2; ++t)
#pragma unroll
            for (int mt = 0; mt < 2; ++mt)
#pragma unroll
                for (int of = 0; of < 4; ++of)
#pragma unroll
                    for (int u = 0; u < 4; ++u) acc[t][mt][of][u] = 0.0f;

#pragma unroll
        for (int ks = 0; ks < 8; ++ks) {
            uint4 a00 = *(const uint4*)&sXf0[(((mtb + 0) * 8 + ks) * 32 + lane) * 4];
            uint4 a01 = *(const uint4*)&sXf0[(((mtb + 1) * 8 + ks) * 32 + lane) * 4];
            uint4 a10 = *(const uint4*)&sXf1[(((mtb + 0) * 8 + ks) * 32 + lane) * 4];
            uint4 a11 = *(const uint4*)&sXf1[(((mtb + 1) * 8 + ks) * 32 + lane) * 4];
#pragma unroll
            for (int of = 0; of < 4; ++of) {
                uint2 bb = *(const uint2*)&sBf[((ks * 16 + ng * 4 + of) * 32 + lane) * 2];
                mma_f16(acc[0][0][of], a00.x, a00.y, a00.z, a00.w, bb.x, bb.y);
                mma_f16(acc[0][1][of], a01.x, a01.y, a01.z, a01.w, bb.x, bb.y);
                mma_f16(acc[1][0][of], a10.x, a10.y, a10.z, a10.w, bb.x, bb.y);
                mma_f16(acc[1][1][of], a11.x, a11.y, a11.z, a11.w, bb.x, bb.y);
            }
        }
        __syncthreads();   // all warps done reading X1 region + (sw1) W2

        if (sw == 1) {     // refill sBf with W3, overlapped with epilogue
#pragma unroll
            for (int u = 0; u < 8; ++u) {
                int idx = tid + u * 256;
                CP_ASYNC16(bf_u32 + idx * 16, (const char*)g_W3h + idx * 16);
            }
            CP_COMMIT();
        }

        // epilogue: bias+lrelu, pack fp16x2, write X2 (pair-plane layout)
#pragma unroll
        for (int t = 0; t < 2; ++t) {
            uint32_t* sXf = t ? sXf1 : sXf0;
#pragma unroll
            for (int mt = 0; mt < 2; ++mt) {
                int gmt = mtb + mt;
#pragma unroll
                for (int of = 0; of < 4; ++of) {
                    int oct = ng * 4 + of;
                    int cb  = oct * 8 + 2 * lc;
                    float e0 = lrelu(acc[t][mt][of][0] + sB2[cb]);
                    float e1 = lrelu(acc[t][mt][of][1] + sB2[cb + 1]);
                    float e2 = lrelu(acc[t][mt][of][2] + sB2[cb]);
                    float e3 = lrelu(acc[t][mt][of][3] + sB2[cb + 1]);
                    uint32_t base = (((gmt * 8 + (oct >> 1)) * 2 + (oct & 1)) * 64 + lane * 2);
                    uint2 w;
                    w.x = pack2(e0, e1);
                    w.y = pack2(e2, e3);
                    *(uint2*)&sXf[base] = w;
                }
            }
        }
        __syncthreads();
    }
    CP_WAIT0();        // W3 resident
    __syncthreads();

    // ===== GEMM2: S_t[c] = sum_j m_j * lrelu(X2_t @ W3 + b3)[j,c] =====
    {
        float cs[2][4][2];
#pragma unroll
        for (int t = 0; t < 2; ++t)
#pragma unroll
            for (int of = 0; of < 4; ++of) { cs[t][of][0] = 0.0f; cs[t][of][1] = 0.0f; }

#pragma unroll
        for (int sw = 0; sw < 2; ++sw) {
            const int mtb = sw * 4 + mg * 2;
            float acc[2][2][4][4];
#pragma unroll
            for (int t = 0; t < 2; ++t)
#pragma unroll
                for (int mt = 0; mt < 2; ++mt)
#pragma unroll
                    for (int of = 0; of < 4; ++of)
#pragma unroll
                        for (int u = 0; u < 4; ++u) acc[t][mt][of][u] = 0.0f;

#pragma unroll
            for (int ks = 0; ks < 8; ++ks) {
                uint32_t base0 = ((mtb + 0) * 8 + ks) * 128 + lane * 2;
                uint32_t base1 = ((mtb + 1) * 8 + ks) * 128 + lane * 2;
                uint2 p00 = *(const uint2*)&sXf0[base0];
                uint2 p01 = *(const uint2*)&sXf0[base0 + 64];
                uint2 p10 = *(const uint2*)&sXf0[base1];
                uint2 p11 = *(const uint2*)&sXf0[base1 + 64];
                uint2 q00 = *(const uint2*)&sXf1[base0];
                uint2 q01 = *(const uint2*)&sXf1[base0 + 64];
                uint2 q10 = *(const uint2*)&sXf1[base1];
                uint2 q11 = *(const uint2*)&sXf1[base1 + 64];
#pragma unroll
                for (int of = 0; of < 4; ++of) {
                    uint2 bb = *(const uint2*)&sBf[((ks * 16 + ng * 4 + of) * 32 + lane) * 2];
                    mma_f16(acc[0][0][of], p00.x, p00.y, p01.x, p01.y, bb.x, bb.y);
                    mma_f16(acc[0][1][of], p10.x, p10.y, p11.x, p11.y, bb.x, bb.y);
                    mma_f16(acc[1][0][of], q00.x, q00.y, q01.x, q01.y, bb.x, bb.y);
                    mma_f16(acc[1][1][of], q10.x, q10.y, q11.x, q11.y, bb.x, bb.y);
                }
            }
            // mask-weighted column sums (accumulate across sweeps)
#pragma unroll
            for (int t = 0; t < 2; ++t)
#pragma unroll
                for (int mt = 0; mt < 2; ++mt) {
                    int r0 = (mtb + mt) * 16 + lr, r1 = r0 + 8;
                    float m0 = sMj[r0], m1 = sMj[r1];
#pragma unroll
                    for (int of = 0; of < 4; ++of) {
                        int cb = (ng * 4 + of) * 8 + 2 * lc;
                        cs[t][of][0] += m0 * lrelu(acc[t][mt][of][0] + sB3[cb])
                                      + m1 * lrelu(acc[t][mt][of][2] + sB3[cb]);
                        cs[t][of][1] += m0 * lrelu(acc[t][mt][of][1] + sB3[cb + 1])
                                      + m1 * lrelu(acc[t][mt][of][3] + sB3[cb + 1]);
                    }
                }
        }
#pragma unroll
        for (int t = 0; t < 2; ++t) {
            float* sS = t ? sS1 : sS0;
#pragma unroll
            for (int of = 0; of < 4; ++of) {
#pragma unroll
                for (int o = 0; o < 2; ++o) {
                    float v = cs[t][of][o];
                    v += __shfl_xor_sync(0xffffffffu, v, 4);
                    v += __shfl_xor_sync(0xffffffffu, v, 8);
                    v += __shfl_xor_sync(0xffffffffu, v, 16);
                    if (lr == 0)
                        atomicAdd(&sS[(ng * 4 + of) * 8 + 2 * lc + o], v);
                }
            }
        }
    }
    __syncthreads();

    // ======= final masked mean + multiply_no_nan + lrelu (both tiles) =======
    {
        int c = tid & 127;
        int t = tid >> 7;
        float miv = sMj[t ? i1 : i0];
        float num = miv * (t ? sS1[c] : sS0[c]);
        float den = miv * sMsum[0];
        float o;
        if (num == 0.0f) o = 0.0f;
        else             o = num / (den == 0.0f ? 1.0f : den);
        out[(t ? bi1 : bi0) * CC + c] = lrelu(o);
    }
}

// ---------------------------------------------------------------------------
extern "C" void kernel_launch(void* const* d_in, const int* in_sizes, int n_in,
                              void* d_out, int out_size) {
    const float* feats = (const float*)d_in[0];
    const int*   mask  = (const int*)d_in[1];
    const float* W1    = (const float*)d_in[2];
    const float* b1    = (const float*)d_in[3];
    const float* W2    = (const float*)d_in[4];
    const float* b2    = (const float*)d_in[5];
    const float* W3    = (const float*)d_in[6];
    const float* b3    = (const float*)d_in[7];
    float* out = (float*)d_out;

    prep_k<<<BN, 128>>>(feats, W1, b1, W2, W3);

    cudaFuncSetAttribute(edge_mlp_k,
                         cudaFuncAttributeMaxDynamicSharedMemorySize,
                         SMEM_TOTAL);
    edge_mlp_k<<<BN / 2, 256, SMEM_TOTAL>>>(mask, b2, b3, out);
}